// round 1
// baseline (speedup 1.0000x reference)
#include <cuda_runtime.h>

// Problem dimensions (fixed per reference)
#define ED 1024           // embedding dim D
#define NH 4              // heads
#define NB 4              // batch
#define SL 2048           // sequence length
#define MT (NB*SL)        // total tokens = 8192

// ---------------- scratch (static device globals; no allocation) -------------
__device__ float g_q[(size_t)NH*NB*SL*ED];       // 128 MB
__device__ float g_k[(size_t)NH*NB*SL*ED];       // 128 MB
__device__ float g_v[(size_t)NH*NB*SL*ED];       // 128 MB
__device__ float g_scores[(size_t)NH*NB*SL*SL];  // 256 MB
__device__ float g_heads[(size_t)NH*NB*SL*ED];   // 128 MB
__device__ float g_proj[(size_t)MT*ED];          // 32 MB
__device__ float g_y[(size_t)MT*ED];             // 32 MB
__device__ float g_t[(size_t)MT*ED];             // 32 MB

// ---------------------------------------------------------------------------
// Generic 128x128 tile SGEMM, BK=8, 256 threads, 8x8 microtile per thread.
// TRANSB=false: C = alpha*A[M,K]@B[K,N]  (B row-major [K,N])
// TRANSB=true : C = alpha*A[M,K]@B^T     (B row-major [N,K])
// Optional bias[N] add, optional accumulate into C.
// Batched over blockIdx.z with element strides sAz/sBz/sCz/sBiasz.
// Requires: M,N multiples of 128; K multiple of 8. (All true here.)
// ---------------------------------------------------------------------------
template <bool TRANSB>
__global__ __launch_bounds__(256) void gemm_kernel(
    const float* __restrict__ A, const float* __restrict__ Bm,
    const float* __restrict__ bias, float* __restrict__ C,
    int M, int N, int K,
    long sAz, long sBz, long sCz, long sBiasz,
    float alpha, int accumulate)
{
    A  += (long)blockIdx.z * sAz;
    Bm += (long)blockIdx.z * sBz;
    C  += (long)blockIdx.z * sCz;
    if (bias) bias += (long)blockIdx.z * sBiasz;

    __shared__ __align__(16) float As[8][128];
    __shared__ __align__(16) float Bs[8][128];

    const int tid = threadIdx.x;
    const int m0 = blockIdx.y * 128;
    const int n0 = blockIdx.x * 128;

    // A-tile (and B-tile when TRANSB): 128 rows x 8 cols, one float4 per thread
    const int arow = tid >> 1;
    const int acol = (tid & 1) * 4;
    // B-tile (NN): 8 rows x 128 cols
    const int brow = tid >> 5;
    const int bcol = (tid & 31) * 4;

    const int ty = tid >> 4;       // 0..15
    const int tx = tid & 15;       // 0..15
    const int cr = ty * 8;
    const int cc = tx * 8;

    float acc[8][8];
    #pragma unroll
    for (int i = 0; i < 8; i++)
        #pragma unroll
        for (int j = 0; j < 8; j++) acc[i][j] = 0.f;

    for (int k0 = 0; k0 < K; k0 += 8) {
        // load A tile (transposed into smem)
        {
            float4 av = *(const float4*)(A + (long)(m0 + arow) * K + k0 + acol);
            As[acol + 0][arow] = av.x;
            As[acol + 1][arow] = av.y;
            As[acol + 2][arow] = av.z;
            As[acol + 3][arow] = av.w;
        }
        // load B tile
        if (TRANSB) {
            float4 bv = *(const float4*)(Bm + (long)(n0 + arow) * K + k0 + acol);
            Bs[acol + 0][arow] = bv.x;
            Bs[acol + 1][arow] = bv.y;
            Bs[acol + 2][arow] = bv.z;
            Bs[acol + 3][arow] = bv.w;
        } else {
            float4 bv = *(const float4*)(Bm + (long)(k0 + brow) * N + n0 + bcol);
            *(float4*)&Bs[brow][bcol] = bv;
        }
        __syncthreads();

        #pragma unroll
        for (int kk = 0; kk < 8; kk++) {
            float a[8], b[8];
            *(float4*)(a)     = *(const float4*)&As[kk][cr];
            *(float4*)(a + 4) = *(const float4*)&As[kk][cr + 4];
            *(float4*)(b)     = *(const float4*)&Bs[kk][cc];
            *(float4*)(b + 4) = *(const float4*)&Bs[kk][cc + 4];
            #pragma unroll
            for (int i = 0; i < 8; i++)
                #pragma unroll
                for (int j = 0; j < 8; j++)
                    acc[i][j] = fmaf(a[i], b[j], acc[i][j]);
        }
        __syncthreads();
    }

    // epilogue
    #pragma unroll
    for (int i = 0; i < 8; i++) {
        float* cp = C + (long)(m0 + cr + i) * N + n0 + cc;
        #pragma unroll
        for (int j = 0; j < 8; j += 4) {
            float4 r;
            r.x = acc[i][j + 0] * alpha;
            r.y = acc[i][j + 1] * alpha;
            r.z = acc[i][j + 2] * alpha;
            r.w = acc[i][j + 3] * alpha;
            if (bias) {
                const float* bp = bias + n0 + cc + j;
                r.x += bp[0]; r.y += bp[1]; r.z += bp[2]; r.w += bp[3];
            }
            if (accumulate) {
                float4 o = *(const float4*)(cp + j);
                r.x += o.x; r.y += o.y; r.z += o.z; r.w += o.w;
            }
            *(float4*)(cp + j) = r;
        }
    }
}

// ---------------------------------------------------------------------------
// Row softmax over length SL, in place. One block (256 threads) per row.
// ---------------------------------------------------------------------------
__global__ __launch_bounds__(256) void softmax_kernel(float* __restrict__ sc)
{
    float* p = sc + (long)blockIdx.x * SL;
    __shared__ float red[256];
    const int t = threadIdx.x;

    float m = -3.4e38f;
    #pragma unroll
    for (int i = t; i < SL; i += 256) m = fmaxf(m, p[i]);
    red[t] = m; __syncthreads();
    for (int s = 128; s > 0; s >>= 1) {
        if (t < s) red[t] = fmaxf(red[t], red[t + s]);
        __syncthreads();
    }
    const float mv = red[0];
    __syncthreads();

    float sum = 0.f;
    #pragma unroll
    for (int i = t; i < SL; i += 256) {
        float e = __expf(p[i] - mv);
        p[i] = e;
        sum += e;
    }
    red[t] = sum; __syncthreads();
    for (int s = 128; s > 0; s >>= 1) {
        if (t < s) red[t] += red[t + s];
        __syncthreads();
    }
    const float inv = 1.f / red[0];
    #pragma unroll
    for (int i = t; i < SL; i += 256) p[i] *= inv;
}

// ---------------------------------------------------------------------------
// out = LayerNorm(X + R) * g + b, row length ED, one block per row.
// ---------------------------------------------------------------------------
__global__ __launch_bounds__(256) void add_ln_kernel(
    const float* __restrict__ X, const float* __restrict__ R,
    const float* __restrict__ g, const float* __restrict__ b,
    float* __restrict__ out)
{
    const long row = blockIdx.x;
    const float* x = X + row * ED;
    const float* r = R + row * ED;
    float* o = out + row * ED;
    const int t = threadIdx.x;

    float v[4];
    float s = 0.f, s2 = 0.f;
    #pragma unroll
    for (int i = 0; i < 4; i++) {
        float h = x[t + i * 256] + r[t + i * 256];
        v[i] = h;
        s += h;
        s2 += h * h;
    }
    __shared__ float rs[256], rq[256];
    rs[t] = s; rq[t] = s2; __syncthreads();
    for (int st = 128; st > 0; st >>= 1) {
        if (t < st) { rs[t] += rs[t + st]; rq[t] += rq[t + st]; }
        __syncthreads();
    }
    const float mean = rs[0] * (1.f / ED);
    const float var  = rq[0] * (1.f / ED) - mean * mean;
    const float inv  = rsqrtf(var + 1e-5f);
    #pragma unroll
    for (int i = 0; i < 4; i++) {
        int c = t + i * 256;
        o[c] = (v[i] - mean) * inv * g[c] + b[c];
    }
}

// ---------------------------------------------------------------------------
extern "C" void kernel_launch(void* const* d_in, const int* in_sizes, int n_in,
                              void* d_out, int out_size)
{
    const float* x   = (const float*)d_in[0];
    const float* Wq  = (const float*)d_in[1];
    const float* bq  = (const float*)d_in[2];
    const float* Wk  = (const float*)d_in[3];
    const float* bk  = (const float*)d_in[4];
    const float* Wv  = (const float*)d_in[5];
    const float* bv  = (const float*)d_in[6];
    const float* W1  = (const float*)d_in[7];
    const float* b1  = (const float*)d_in[8];
    const float* g1  = (const float*)d_in[9];
    const float* be1 = (const float*)d_in[10];
    const float* W2  = (const float*)d_in[11];
    const float* b2  = (const float*)d_in[12];
    const float* g2  = (const float*)d_in[13];
    const float* be2 = (const float*)d_in[14];
    float* out = (float*)d_out;

    float *q, *k, *v, *sc, *hd, *proj, *y, *tp;
    cudaGetSymbolAddress((void**)&q,    g_q);
    cudaGetSymbolAddress((void**)&k,    g_k);
    cudaGetSymbolAddress((void**)&v,    g_v);
    cudaGetSymbolAddress((void**)&sc,   g_scores);
    cudaGetSymbolAddress((void**)&hd,   g_heads);
    cudaGetSymbolAddress((void**)&proj, g_proj);
    cudaGetSymbolAddress((void**)&y,    g_y);
    cudaGetSymbolAddress((void**)&tp,   g_t);

    const float scale = 1.0f / 32.0f;   // 1/sqrt(1024)
    const long  hstride = (long)NB * SL * ED;   // per-head slice of q/k/v/heads
    dim3 blk(256);

    // ---- per-head Q/K/V projections: x[8192,1024] @ W[h][1024,1024] + b[h]
    {
        dim3 grid(ED / 128, MT / 128, NH);
        gemm_kernel<false><<<grid, blk>>>(x, Wq, bq, q, MT, ED, ED,
                                          0L, (long)ED * ED, hstride, (long)ED, 1.f, 0);
        gemm_kernel<false><<<grid, blk>>>(x, Wk, bk, k, MT, ED, ED,
                                          0L, (long)ED * ED, hstride, (long)ED, 1.f, 0);
        gemm_kernel<false><<<grid, blk>>>(x, Wv, bv, v, MT, ED, ED,
                                          0L, (long)ED * ED, hstride, (long)ED, 1.f, 0);
    }

    // ---- scores[h,b] = scale * q[h,b] @ k[h,b]^T   (batched over h*b = 16)
    {
        dim3 grid(SL / 128, SL / 128, NH * NB);
        gemm_kernel<true><<<grid, blk>>>(q, k, nullptr, sc, SL, SL, ED,
                                         (long)SL * ED, (long)SL * ED, (long)SL * SL, 0L,
                                         scale, 0);
    }

    // ---- row softmax over SL
    softmax_kernel<<<NH * NB * SL, blk>>>(sc);

    // ---- heads[h,b] = attn @ v[h,b]
    {
        dim3 grid(ED / 128, SL / 128, NH * NB);
        gemm_kernel<false><<<grid, blk>>>(sc, v, nullptr, hd, SL, ED, SL,
                                          (long)SL * SL, (long)SL * ED, (long)SL * ED, 0L,
                                          1.f, 0);
    }

    // ---- proj = concat(heads) @ W1 + b1 == sum_h heads[h] @ W1[h*D:(h+1)*D,:]
    for (int h = 0; h < NH; h++) {
        dim3 grid(ED / 128, MT / 128, 1);
        gemm_kernel<false><<<grid, blk>>>(hd + (long)h * hstride,
                                          W1 + (long)h * ED * ED,
                                          (h == 0) ? b1 : nullptr, proj,
                                          MT, ED, ED, 0L, 0L, 0L, 0L,
                                          1.f, (h > 0) ? 1 : 0);
    }

    // ---- y = LN(x + proj)
    add_ln_kernel<<<MT, blk>>>(x, proj, g1, be1, y);

    // ---- t = y @ W2 + b2
    {
        dim3 grid(ED / 128, MT / 128, 1);
        gemm_kernel<false><<<grid, blk>>>(y, W2, b2, tp, MT, ED, ED,
                                          0L, 0L, 0L, 0L, 1.f, 0);
    }

    // ---- out = LN(y + t)
    add_ln_kernel<<<MT, blk>>>(y, tp, g2, be2, out);
}

// round 4
// speedup vs baseline: 2.1573x; 2.1573x over previous
#include <cuda_runtime.h>
#include <cstdint>

// Problem dimensions (fixed per reference)
#define ED 1024           // embedding dim D
#define NH 4              // heads
#define NB 4              // batch
#define SL 2048           // sequence length
#define MT (NB*SL)        // total tokens = 8192

// ---------------- scratch (static device globals; no allocation) -------------
__device__ float g_q[(size_t)NH*NB*SL*ED];
__device__ float g_k[(size_t)NH*NB*SL*ED];
__device__ float g_v[(size_t)NH*NB*SL*ED];
__device__ float g_scores[(size_t)NH*NB*SL*SL];
__device__ float g_heads[(size_t)NH*NB*SL*ED];
__device__ float g_proj[(size_t)MT*ED];
__device__ float g_y[(size_t)MT*ED];
__device__ float g_t[(size_t)MT*ED];

// ---------------------------------------------------------------------------
__device__ __forceinline__ uint32_t f2tf32(float f) {
    uint32_t r;
    asm("cvt.rna.tf32.f32 %0, %1;" : "=r"(r) : "f"(f));
    return r;
}

// ---------------------------------------------------------------------------
// TF32 tensor-core GEMM.
// Block tile 128x128, BK=32, 256 threads = 8 warps, warp tile 64x32
// (warps laid out 2 (M) x 4 (N)), each warp = 4x4 grid of m16n8k8 mma tiles.
// TRANSB=false: C = alpha*A[M,K]@B[K,N] ; TRANSB=true: B is [N,K] (B^T).
// Optional bias[N] (offset by z*sBiasz), optional accumulate. Batched over z.
// Requires M,N % 128 == 0, K % 32 == 0.
// ---------------------------------------------------------------------------
template <bool TRANSB>
__global__ __launch_bounds__(256) void gemm_tf32_kernel(
    const float* __restrict__ A, const float* __restrict__ Bm,
    const float* __restrict__ bias, float* __restrict__ C,
    int M, int N, int K,
    long sAz, long sBz, long sCz, long sBiasz,
    float alpha, int accumulate)
{
    A  += (long)blockIdx.z * sAz;
    Bm += (long)blockIdx.z * sBz;
    C  += (long)blockIdx.z * sCz;
    if (bias) bias += (long)blockIdx.z * sBiasz;

    // [k][m] and [k][n], padded stride 132 (mod-32 bank skew of 4)
    __shared__ uint32_t As[32][132];
    __shared__ uint32_t Bs[32][132];

    const int tid  = threadIdx.x;
    const int lane = tid & 31;
    const int warp = tid >> 5;
    const int g    = lane >> 2;   // group id (0..7)
    const int t    = lane & 3;    // thread-in-group (0..3)

    const int m0 = blockIdx.y * 128;
    const int n0 = blockIdx.x * 128;
    const int wm = (warp >> 2) * 64;   // warp M offset (0 or 64)
    const int wn = (warp & 3) * 32;    // warp N offset (0..96)

    // A (and B when TRANSB): 128 rows x 8 k per pass, transpose into smem
    const int arow  = tid >> 1;        // 0..127
    const int acol4 = (tid & 1) * 4;   // 0 or 4
    // B (NN): 8 k-rows x 128 cols per pass
    const int brow  = tid >> 5;        // 0..7
    const int bcol  = (tid & 31) * 4;  // 0..124

    float acc[4][4][4];
    #pragma unroll
    for (int mi = 0; mi < 4; mi++)
        #pragma unroll
        for (int ni = 0; ni < 4; ni++)
            #pragma unroll
            for (int r = 0; r < 4; r++) acc[mi][ni][r] = 0.f;

    for (int k0 = 0; k0 < K; k0 += 32) {
        // ---- load A tile (transposed), convert to tf32
        #pragma unroll
        for (int p = 0; p < 4; p++) {
            float4 av = *(const float4*)(A + (long)(m0 + arow) * K + k0 + p * 8 + acol4);
            As[p * 8 + acol4 + 0][arow] = f2tf32(av.x);
            As[p * 8 + acol4 + 1][arow] = f2tf32(av.y);
            As[p * 8 + acol4 + 2][arow] = f2tf32(av.z);
            As[p * 8 + acol4 + 3][arow] = f2tf32(av.w);
        }
        // ---- load B tile
        if (TRANSB) {
            #pragma unroll
            for (int p = 0; p < 4; p++) {
                float4 bv = *(const float4*)(Bm + (long)(n0 + arow) * K + k0 + p * 8 + acol4);
                Bs[p * 8 + acol4 + 0][arow] = f2tf32(bv.x);
                Bs[p * 8 + acol4 + 1][arow] = f2tf32(bv.y);
                Bs[p * 8 + acol4 + 2][arow] = f2tf32(bv.z);
                Bs[p * 8 + acol4 + 3][arow] = f2tf32(bv.w);
            }
        } else {
            #pragma unroll
            for (int p = 0; p < 4; p++) {
                float4 bv = *(const float4*)(Bm + (long)(k0 + p * 8 + brow) * N + n0 + bcol);
                uint4 u;
                u.x = f2tf32(bv.x); u.y = f2tf32(bv.y);
                u.z = f2tf32(bv.z); u.w = f2tf32(bv.w);
                *(uint4*)&Bs[p * 8 + brow][bcol] = u;
            }
        }
        __syncthreads();

        #pragma unroll
        for (int kk = 0; kk < 32; kk += 8) {
            uint32_t af[4][4], bf[4][2];
            #pragma unroll
            for (int mi = 0; mi < 4; mi++) {
                const int mc = wm + mi * 16 + g;
                af[mi][0] = As[kk + t][mc];
                af[mi][1] = As[kk + t][mc + 8];
                af[mi][2] = As[kk + t + 4][mc];
                af[mi][3] = As[kk + t + 4][mc + 8];
            }
            #pragma unroll
            for (int ni = 0; ni < 4; ni++) {
                const int nc = wn + ni * 8 + g;
                bf[ni][0] = Bs[kk + t][nc];
                bf[ni][1] = Bs[kk + t + 4][nc];
            }
            #pragma unroll
            for (int mi = 0; mi < 4; mi++)
                #pragma unroll
                for (int ni = 0; ni < 4; ni++) {
                    asm volatile(
                        "mma.sync.aligned.m16n8k8.row.col.f32.tf32.tf32.f32 "
                        "{%0,%1,%2,%3}, {%4,%5,%6,%7}, {%8,%9}, {%0,%1,%2,%3};"
                        : "+f"(acc[mi][ni][0]), "+f"(acc[mi][ni][1]),
                          "+f"(acc[mi][ni][2]), "+f"(acc[mi][ni][3])
                        : "r"(af[mi][0]), "r"(af[mi][1]), "r"(af[mi][2]), "r"(af[mi][3]),
                          "r"(bf[ni][0]), "r"(bf[ni][1]));
                }
        }
        __syncthreads();
    }

    // ---- epilogue
    #pragma unroll
    for (int mi = 0; mi < 4; mi++) {
        #pragma unroll
        for (int ni = 0; ni < 4; ni++) {
            const int col = n0 + wn + ni * 8 + 2 * t;
            #pragma unroll
            for (int h = 0; h < 2; h++) {           // h=0 -> c0/c1, h=1 -> c2/c3
                const int row = m0 + wm + mi * 16 + g + h * 8;
                float2 r;
                r.x = acc[mi][ni][h * 2 + 0] * alpha;
                r.y = acc[mi][ni][h * 2 + 1] * alpha;
                if (bias) {
                    r.x += bias[col];
                    r.y += bias[col + 1];
                }
                float* cp = C + (long)row * N + col;
                if (accumulate) {
                    float2 o = *(const float2*)cp;
                    r.x += o.x; r.y += o.y;
                }
                *(float2*)cp = r;
            }
        }
    }
}

// ---------------------------------------------------------------------------
// Single-pass row softmax over SL=2048, in place. 256 threads, 8 vals/thread.
// ---------------------------------------------------------------------------
__global__ __launch_bounds__(256) void softmax_kernel(float* __restrict__ sc)
{
    float4* p4 = (float4*)(sc + (long)blockIdx.x * SL);
    const int tid = threadIdx.x;
    const int lane = tid & 31;
    const int warp = tid >> 5;
    __shared__ float red[8];

    float4 v0 = p4[tid];
    float4 v1 = p4[tid + 256];

    float m = fmaxf(fmaxf(fmaxf(v0.x, v0.y), fmaxf(v0.z, v0.w)),
                    fmaxf(fmaxf(v1.x, v1.y), fmaxf(v1.z, v1.w)));
    #pragma unroll
    for (int s = 16; s > 0; s >>= 1) m = fmaxf(m, __shfl_xor_sync(0xffffffffu, m, s));
    if (lane == 0) red[warp] = m;
    __syncthreads();
    if (warp == 0) {
        float mm = red[lane & 7];
        #pragma unroll
        for (int s = 4; s > 0; s >>= 1) mm = fmaxf(mm, __shfl_xor_sync(0xffffffffu, mm, s));
        if (lane == 0) red[0] = mm;
    }
    __syncthreads();
    const float mv = red[0];
    __syncthreads();

    v0.x = __expf(v0.x - mv); v0.y = __expf(v0.y - mv);
    v0.z = __expf(v0.z - mv); v0.w = __expf(v0.w - mv);
    v1.x = __expf(v1.x - mv); v1.y = __expf(v1.y - mv);
    v1.z = __expf(v1.z - mv); v1.w = __expf(v1.w - mv);
    float s = v0.x + v0.y + v0.z + v0.w + v1.x + v1.y + v1.z + v1.w;
    #pragma unroll
    for (int st = 16; st > 0; st >>= 1) s += __shfl_xor_sync(0xffffffffu, s, st);
    if (lane == 0) red[warp] = s;
    __syncthreads();
    if (warp == 0) {
        float ss = red[lane & 7];
        #pragma unroll
        for (int st = 4; st > 0; st >>= 1) ss += __shfl_xor_sync(0xffffffffu, ss, st);
        if (lane == 0) red[0] = ss;
    }
    __syncthreads();
    const float inv = 1.f / red[0];

    v0.x *= inv; v0.y *= inv; v0.z *= inv; v0.w *= inv;
    v1.x *= inv; v1.y *= inv; v1.z *= inv; v1.w *= inv;
    p4[tid] = v0;
    p4[tid + 256] = v1;
}

// ---------------------------------------------------------------------------
// out = LayerNorm(X + R) * g + b, row length ED, one block per row.
// ---------------------------------------------------------------------------
__global__ __launch_bounds__(256) void add_ln_kernel(
    const float* __restrict__ X, const float* __restrict__ R,
    const float* __restrict__ g, const float* __restrict__ b,
    float* __restrict__ out)
{
    const long row = blockIdx.x;
    const float* x = X + row * ED;
    const float* r = R + row * ED;
    float* o = out + row * ED;
    const int t = threadIdx.x;

    float v[4];
    float s = 0.f, s2 = 0.f;
    #pragma unroll
    for (int i = 0; i < 4; i++) {
        float h = x[t + i * 256] + r[t + i * 256];
        v[i] = h;
        s += h;
        s2 += h * h;
    }
    __shared__ float rs[256], rq[256];
    rs[t] = s; rq[t] = s2; __syncthreads();
    for (int st = 128; st > 0; st >>= 1) {
        if (t < st) { rs[t] += rs[t + st]; rq[t] += rq[t + st]; }
        __syncthreads();
    }
    const float mean = rs[0] * (1.f / ED);
    const float var  = rq[0] * (1.f / ED) - mean * mean;
    const float inv  = rsqrtf(var + 1e-5f);
    #pragma unroll
    for (int i = 0; i < 4; i++) {
        int c = t + i * 256;
        o[c] = (v[i] - mean) * inv * g[c] + b[c];
    }
}

// ---------------------------------------------------------------------------
extern "C" void kernel_launch(void* const* d_in, const int* in_sizes, int n_in,
                              void* d_out, int out_size)
{
    const float* x   = (const float*)d_in[0];
    const float* Wq  = (const float*)d_in[1];
    const float* bq  = (const float*)d_in[2];
    const float* Wk  = (const float*)d_in[3];
    const float* bk  = (const float*)d_in[4];
    const float* Wv  = (const float*)d_in[5];
    const float* bv  = (const float*)d_in[6];
    const float* W1  = (const float*)d_in[7];
    const float* b1  = (const float*)d_in[8];
    const float* g1  = (const float*)d_in[9];
    const float* be1 = (const float*)d_in[10];
    const float* W2  = (const float*)d_in[11];
    const float* b2  = (const float*)d_in[12];
    const float* g2  = (const float*)d_in[13];
    const float* be2 = (const float*)d_in[14];
    float* out = (float*)d_out;

    float *q, *k, *v, *sc, *hd, *proj, *y, *tp;
    cudaGetSymbolAddress((void**)&q,    g_q);
    cudaGetSymbolAddress((void**)&k,    g_k);
    cudaGetSymbolAddress((void**)&v,    g_v);
    cudaGetSymbolAddress((void**)&sc,   g_scores);
    cudaGetSymbolAddress((void**)&hd,   g_heads);
    cudaGetSymbolAddress((void**)&proj, g_proj);
    cudaGetSymbolAddress((void**)&y,    g_y);
    cudaGetSymbolAddress((void**)&tp,   g_t);

    const float scale = 1.0f / 32.0f;   // 1/sqrt(1024)
    const long  hstride = (long)NB * SL * ED;
    dim3 blk(256);

    // ---- per-head Q/K/V projections (batched over H); bias offset h*ED !
    {
        dim3 grid(ED / 128, MT / 128, NH);
        gemm_tf32_kernel<false><<<grid, blk>>>(x, Wq, bq, q, MT, ED, ED,
                                               0L, (long)ED * ED, hstride, (long)ED, 1.f, 0);
        gemm_tf32_kernel<false><<<grid, blk>>>(x, Wk, bk, k, MT, ED, ED,
                                               0L, (long)ED * ED, hstride, (long)ED, 1.f, 0);
        gemm_tf32_kernel<false><<<grid, blk>>>(x, Wv, bv, v, MT, ED, ED,
                                               0L, (long)ED * ED, hstride, (long)ED, 1.f, 0);
    }

    // ---- scores = scale * q @ k^T  (batched over H*B = 16)
    {
        dim3 grid(SL / 128, SL / 128, NH * NB);
        gemm_tf32_kernel<true><<<grid, blk>>>(q, k, nullptr, sc, SL, SL, ED,
                                              (long)SL * ED, (long)SL * ED, (long)SL * SL, 0L,
                                              scale, 0);
    }

    // ---- row softmax
    softmax_kernel<<<NH * NB * SL, blk>>>(sc);

    // ---- heads = attn @ v
    {
        dim3 grid(ED / 128, SL / 128, NH * NB);
        gemm_tf32_kernel<false><<<grid, blk>>>(sc, v, nullptr, hd, SL, ED, SL,
                                               (long)SL * SL, (long)SL * ED, (long)SL * ED, 0L,
                                               1.f, 0);
    }

    // ---- proj = concat(heads) @ W1 + b1 == sum_h heads[h] @ W1[h*D:(h+1)*D,:]
    for (int h = 0; h < NH; h++) {
        dim3 grid(ED / 128, MT / 128, 1);
        gemm_tf32_kernel<false><<<grid, blk>>>(hd + (long)h * hstride,
                                               W1 + (long)h * ED * ED,
                                               (h == 0) ? b1 : nullptr, proj,
                                               MT, ED, ED, 0L, 0L, 0L, 0L,
                                               1.f, (h > 0) ? 1 : 0);
    }

    // ---- y = LN(x + proj)
    add_ln_kernel<<<MT, blk>>>(x, proj, g1, be1, y);

    // ---- t = y @ W2 + b2
    {
        dim3 grid(ED / 128, MT / 128, 1);
        gemm_tf32_kernel<false><<<grid, blk>>>(y, W2, b2, tp, MT, ED, ED,
                                               0L, 0L, 0L, 0L, 1.f, 0);
    }

    // ---- out = LN(y + t)
    add_ln_kernel<<<MT, blk>>>(y, tp, g2, be2, out);
}

// round 5
// speedup vs baseline: 2.6466x; 1.2268x over previous
#include <cuda_runtime.h>
#include <cstdint>

// Problem dimensions (fixed per reference)
#define ED 1024           // embedding dim D
#define NH 4              // heads
#define NB 4              // batch
#define SL 2048           // sequence length
#define MT (NB*SL)        // total tokens = 8192

// ---------------- scratch (static device globals; no allocation) -------------
__device__ float g_q[(size_t)NH*NB*SL*ED];
__device__ float g_k[(size_t)NH*NB*SL*ED];
__device__ float g_v[(size_t)NH*NB*SL*ED];
__device__ float g_scores[(size_t)NH*NB*SL*SL];
__device__ float g_heads[(size_t)NH*NB*SL*ED];
__device__ float g_proj[(size_t)MT*ED];
__device__ float g_y[(size_t)MT*ED];
__device__ float g_t[(size_t)MT*ED];

// ---------------------------------------------------------------------------
__device__ __forceinline__ uint32_t f2tf32(float f) {
    uint32_t r;
    asm("cvt.rna.tf32.f32 %0, %1;" : "=r"(r) : "f"(f));
    return r;
}

__device__ __forceinline__ void mma_tf32(float* acc, const uint32_t* a, const uint32_t* b)
{
    asm volatile(
        "mma.sync.aligned.m16n8k8.row.col.f32.tf32.tf32.f32 "
        "{%0,%1,%2,%3}, {%4,%5,%6,%7}, {%8,%9}, {%0,%1,%2,%3};"
        : "+f"(acc[0]), "+f"(acc[1]), "+f"(acc[2]), "+f"(acc[3])
        : "r"(a[0]), "r"(a[1]), "r"(a[2]), "r"(a[3]), "r"(b[0]), "r"(b[1]));
}

// smem geometry (uint32 words)
#define A_STRIDE 136                 // 128 + 8  (stride mod 32 == 8)
#define B_STRIDE 264                 // 256 + 8
#define A_WORDS  (16 * A_STRIDE)     // 2176
#define B_WORDS  (16 * B_STRIDE)     // 4224
#define STAGE_WORDS (A_WORDS + B_WORDS)  // 6400
#define SMEM_BYTES (2 * STAGE_WORDS * 4) // 51200

// ---------------------------------------------------------------------------
// TF32 tensor-core GEMM, double-buffered.
// Block tile 128(M) x 256(N), BK=16, 256 threads = 8 warps, warp tile 64x64
// (2 M-warps x 4 N-warps), each warp = 4x8 grid of m16n8k8 mma tiles.
// Smem layouts: A [k(16)][m(128)], B [k(16)][n(256)], both XOR-swizzled:
//   physical col = col ^ (((k>>2)&3)<<3)   -> conflict-free STS and LDS.
// TRANSB=false: C = alpha*A[M,K]@B[K,N] ; TRANSB=true: B is [N,K] (B^T).
// Optional bias[N] (offset z*sBiasz), optional accumulate. Batched over z.
// Requires M % 128 == 0, N % 256 == 0, K % 16 == 0.
// ---------------------------------------------------------------------------
template <bool TRANSB>
__global__ __launch_bounds__(256) void gemm_tf32_kernel(
    const float* __restrict__ A, const float* __restrict__ Bm,
    const float* __restrict__ bias, float* __restrict__ C,
    int M, int N, int K,
    long sAz, long sBz, long sCz, long sBiasz,
    float alpha, int accumulate)
{
    extern __shared__ uint32_t smem[];

    A  += (long)blockIdx.z * sAz;
    Bm += (long)blockIdx.z * sBz;
    C  += (long)blockIdx.z * sCz;
    if (bias) bias += (long)blockIdx.z * sBiasz;

    const int tid  = threadIdx.x;
    const int lane = tid & 31;
    const int warp = tid >> 5;
    const int g    = lane >> 2;   // 0..7
    const int t    = lane & 3;    // 0..3

    const int m0 = blockIdx.y * 128;
    const int n0 = blockIdx.x * 256;
    const int wm = (warp >> 2) * 64;   // M offset (0 or 64)
    const int wn = (warp & 3) * 64;    // N offset (0,64,128,192)

    float acc[4][8][4];
    #pragma unroll
    for (int mi = 0; mi < 4; mi++)
        #pragma unroll
        for (int ni = 0; ni < 8; ni++)
            #pragma unroll
            for (int r = 0; r < 4; r++) acc[mi][ni][r] = 0.f;

    const int KT = K >> 4;

    // register staging for the gmem tiles
    float4 aA[2], bB[4];

    // ---- prologue: load tile 0
    {
        #pragma unroll
        for (int p = 0; p < 2; p++) {
            int c = tid + p * 256; int m = c >> 2; int j = c & 3;
            aA[p] = *(const float4*)(A + (long)(m0 + m) * K + 4 * j);
        }
        if (TRANSB) {
            #pragma unroll
            for (int p = 0; p < 4; p++) {
                int c = tid + p * 256; int n = c >> 2; int j = c & 3;
                bB[p] = *(const float4*)(Bm + (long)(n0 + n) * K + 4 * j);
            }
        } else {
            #pragma unroll
            for (int p = 0; p < 4; p++) {
                int c = tid + p * 256; int k = c >> 6; int jn = c & 63;
                bB[p] = *(const float4*)(Bm + (long)k * N + n0 + 4 * jn);
            }
        }
    }

    for (int kt = 0; kt < KT; kt++) {
        uint32_t* Sa = smem + (kt & 1) * STAGE_WORDS;
        uint32_t* Sb = Sa + A_WORDS;

        // ---- STS current tile (cvt to tf32, swizzled scatter)
        #pragma unroll
        for (int p = 0; p < 2; p++) {
            int c = tid + p * 256; int m = c >> 2; int j = c & 3;
            const float* av = (const float*)&aA[p];
            const int sw = (j & 3) << 3;
            #pragma unroll
            for (int i = 0; i < 4; i++)
                Sa[(4 * j + i) * A_STRIDE + (m ^ sw)] = f2tf32(av[i]);
        }
        if (TRANSB) {
            #pragma unroll
            for (int p = 0; p < 4; p++) {
                int c = tid + p * 256; int n = c >> 2; int j = c & 3;
                const float* bv = (const float*)&bB[p];
                const int sw = (j & 3) << 3;
                #pragma unroll
                for (int i = 0; i < 4; i++)
                    Sb[(4 * j + i) * B_STRIDE + (n ^ sw)] = f2tf32(bv[i]);
            }
        } else {
            #pragma unroll
            for (int p = 0; p < 4; p++) {
                int c = tid + p * 256; int k = c >> 6; int jn = c & 63;
                const float* bv = (const float*)&bB[p];
                const int colb = (4 * jn) ^ (((k >> 2) & 3) << 3);
                uint4 u;
                u.x = f2tf32(bv[0]); u.y = f2tf32(bv[1]);
                u.z = f2tf32(bv[2]); u.w = f2tf32(bv[3]);
                *(uint4*)&Sb[k * B_STRIDE + colb] = u;
            }
        }
        __syncthreads();

        // ---- prefetch next tile into registers (overlapped with MMA below)
        if (kt + 1 < KT) {
            const int k0 = (kt + 1) << 4;
            #pragma unroll
            for (int p = 0; p < 2; p++) {
                int c = tid + p * 256; int m = c >> 2; int j = c & 3;
                aA[p] = *(const float4*)(A + (long)(m0 + m) * K + k0 + 4 * j);
            }
            if (TRANSB) {
                #pragma unroll
                for (int p = 0; p < 4; p++) {
                    int c = tid + p * 256; int n = c >> 2; int j = c & 3;
                    bB[p] = *(const float4*)(Bm + (long)(n0 + n) * K + k0 + 4 * j);
                }
            } else {
                #pragma unroll
                for (int p = 0; p < 4; p++) {
                    int c = tid + p * 256; int k = c >> 6; int jn = c & 63;
                    bB[p] = *(const float4*)(Bm + (long)(k0 + k) * N + n0 + 4 * jn);
                }
            }
        }

        // ---- MMA over current stage
        #pragma unroll
        for (int kk = 0; kk < 16; kk += 8) {
            const int r0 = kk + t, r1 = kk + t + 4;
            const int s0 = ((r0 >> 2) & 3) << 3;
            const int s1 = ((r1 >> 2) & 3) << 3;
            uint32_t af[4][4], bf[8][2];
            #pragma unroll
            for (int mi = 0; mi < 4; mi++) {
                const int mc = wm + mi * 16 + g;
                af[mi][0] = Sa[r0 * A_STRIDE + (mc ^ s0)];
                af[mi][1] = Sa[r0 * A_STRIDE + ((mc + 8) ^ s0)];
                af[mi][2] = Sa[r1 * A_STRIDE + (mc ^ s1)];
                af[mi][3] = Sa[r1 * A_STRIDE + ((mc + 8) ^ s1)];
            }
            #pragma unroll
            for (int ni = 0; ni < 8; ni++) {
                const int nc = wn + ni * 8 + g;
                bf[ni][0] = Sb[r0 * B_STRIDE + (nc ^ s0)];
                bf[ni][1] = Sb[r1 * B_STRIDE + (nc ^ s1)];
            }
            #pragma unroll
            for (int mi = 0; mi < 4; mi++)
                #pragma unroll
                for (int ni = 0; ni < 8; ni++)
                    mma_tf32(acc[mi][ni], af[mi], bf[ni]);
        }
    }

    // ---- epilogue
    #pragma unroll
    for (int mi = 0; mi < 4; mi++) {
        #pragma unroll
        for (int ni = 0; ni < 8; ni++) {
            const int col = n0 + wn + ni * 8 + 2 * t;
            #pragma unroll
            for (int h = 0; h < 2; h++) {           // h=0 -> c0/c1, h=1 -> c2/c3
                const int row = m0 + wm + mi * 16 + g + h * 8;
                float2 r;
                r.x = acc[mi][ni][h * 2 + 0] * alpha;
                r.y = acc[mi][ni][h * 2 + 1] * alpha;
                if (bias) {
                    r.x += bias[col];
                    r.y += bias[col + 1];
                }
                float* cp = C + (long)row * N + col;
                if (accumulate) {
                    float2 o = *(const float2*)cp;
                    r.x += o.x; r.y += o.y;
                }
                *(float2*)cp = r;
            }
        }
    }
}

// ---------------------------------------------------------------------------
// Single-pass row softmax over SL=2048, in place. 256 threads, 8 vals/thread.
// ---------------------------------------------------------------------------
__global__ __launch_bounds__(256) void softmax_kernel(float* __restrict__ sc)
{
    float4* p4 = (float4*)(sc + (long)blockIdx.x * SL);
    const int tid = threadIdx.x;
    const int lane = tid & 31;
    const int warp = tid >> 5;
    __shared__ float red[8];

    float4 v0 = p4[tid];
    float4 v1 = p4[tid + 256];

    float m = fmaxf(fmaxf(fmaxf(v0.x, v0.y), fmaxf(v0.z, v0.w)),
                    fmaxf(fmaxf(v1.x, v1.y), fmaxf(v1.z, v1.w)));
    #pragma unroll
    for (int s = 16; s > 0; s >>= 1) m = fmaxf(m, __shfl_xor_sync(0xffffffffu, m, s));
    if (lane == 0) red[warp] = m;
    __syncthreads();
    if (warp == 0) {
        float mm = red[lane & 7];
        #pragma unroll
        for (int s = 4; s > 0; s >>= 1) mm = fmaxf(mm, __shfl_xor_sync(0xffffffffu, mm, s));
        if (lane == 0) red[0] = mm;
    }
    __syncthreads();
    const float mv = red[0];
    __syncthreads();

    v0.x = __expf(v0.x - mv); v0.y = __expf(v0.y - mv);
    v0.z = __expf(v0.z - mv); v0.w = __expf(v0.w - mv);
    v1.x = __expf(v1.x - mv); v1.y = __expf(v1.y - mv);
    v1.z = __expf(v1.z - mv); v1.w = __expf(v1.w - mv);
    float s = v0.x + v0.y + v0.z + v0.w + v1.x + v1.y + v1.z + v1.w;
    #pragma unroll
    for (int st = 16; st > 0; st >>= 1) s += __shfl_xor_sync(0xffffffffu, s, st);
    if (lane == 0) red[warp] = s;
    __syncthreads();
    if (warp == 0) {
        float ss = red[lane & 7];
        #pragma unroll
        for (int st = 4; st > 0; st >>= 1) ss += __shfl_xor_sync(0xffffffffu, ss, st);
        if (lane == 0) red[0] = ss;
    }
    __syncthreads();
    const float inv = 1.f / red[0];

    v0.x *= inv; v0.y *= inv; v0.z *= inv; v0.w *= inv;
    v1.x *= inv; v1.y *= inv; v1.z *= inv; v1.w *= inv;
    p4[tid] = v0;
    p4[tid + 256] = v1;
}

// ---------------------------------------------------------------------------
// out = LayerNorm(X + R) * g + b, row length ED, one block per row.
// ---------------------------------------------------------------------------
__global__ __launch_bounds__(256) void add_ln_kernel(
    const float* __restrict__ X, const float* __restrict__ R,
    const float* __restrict__ g, const float* __restrict__ b,
    float* __restrict__ out)
{
    const long row = blockIdx.x;
    const float* x = X + row * ED;
    const float* r = R + row * ED;
    float* o = out + row * ED;
    const int t = threadIdx.x;

    float v[4];
    float s = 0.f, s2 = 0.f;
    #pragma unroll
    for (int i = 0; i < 4; i++) {
        float h = x[t + i * 256] + r[t + i * 256];
        v[i] = h;
        s += h;
        s2 += h * h;
    }
    __shared__ float rs[256], rq[256];
    rs[t] = s; rq[t] = s2; __syncthreads();
    for (int st = 128; st > 0; st >>= 1) {
        if (t < st) { rs[t] += rs[t + st]; rq[t] += rq[t + st]; }
        __syncthreads();
    }
    const float mean = rs[0] * (1.f / ED);
    const float var  = rq[0] * (1.f / ED) - mean * mean;
    const float inv  = rsqrtf(var + 1e-5f);
    #pragma unroll
    for (int i = 0; i < 4; i++) {
        int c = t + i * 256;
        o[c] = (v[i] - mean) * inv * g[c] + b[c];
    }
}

// ---------------------------------------------------------------------------
extern "C" void kernel_launch(void* const* d_in, const int* in_sizes, int n_in,
                              void* d_out, int out_size)
{
    const float* x   = (const float*)d_in[0];
    const float* Wq  = (const float*)d_in[1];
    const float* bq  = (const float*)d_in[2];
    const float* Wk  = (const float*)d_in[3];
    const float* bk  = (const float*)d_in[4];
    const float* Wv  = (const float*)d_in[5];
    const float* bv  = (const float*)d_in[6];
    const float* W1  = (const float*)d_in[7];
    const float* b1  = (const float*)d_in[8];
    const float* g1  = (const float*)d_in[9];
    const float* be1 = (const float*)d_in[10];
    const float* W2  = (const float*)d_in[11];
    const float* b2  = (const float*)d_in[12];
    const float* g2  = (const float*)d_in[13];
    const float* be2 = (const float*)d_in[14];
    float* out = (float*)d_out;

    float *q, *k, *v, *sc, *hd, *proj, *y, *tp;
    cudaGetSymbolAddress((void**)&q,    g_q);
    cudaGetSymbolAddress((void**)&k,    g_k);
    cudaGetSymbolAddress((void**)&v,    g_v);
    cudaGetSymbolAddress((void**)&sc,   g_scores);
    cudaGetSymbolAddress((void**)&hd,   g_heads);
    cudaGetSymbolAddress((void**)&proj, g_proj);
    cudaGetSymbolAddress((void**)&y,    g_y);
    cudaGetSymbolAddress((void**)&tp,   g_t);

    // allow 50KB dynamic smem (deterministic; called every time)
    cudaFuncSetAttribute(gemm_tf32_kernel<false>,
                         cudaFuncAttributeMaxDynamicSharedMemorySize, SMEM_BYTES);
    cudaFuncSetAttribute(gemm_tf32_kernel<true>,
                         cudaFuncAttributeMaxDynamicSharedMemorySize, SMEM_BYTES);

    const float scale = 1.0f / 32.0f;   // 1/sqrt(1024)
    const long  hstride = (long)NB * SL * ED;
    dim3 blk(256);

    // ---- per-head Q/K/V projections (batched over H); bias offset h*ED
    {
        dim3 grid(ED / 256, MT / 128, NH);
        gemm_tf32_kernel<false><<<grid, blk, SMEM_BYTES>>>(x, Wq, bq, q, MT, ED, ED,
                                               0L, (long)ED * ED, hstride, (long)ED, 1.f, 0);
        gemm_tf32_kernel<false><<<grid, blk, SMEM_BYTES>>>(x, Wk, bk, k, MT, ED, ED,
                                               0L, (long)ED * ED, hstride, (long)ED, 1.f, 0);
        gemm_tf32_kernel<false><<<grid, blk, SMEM_BYTES>>>(x, Wv, bv, v, MT, ED, ED,
                                               0L, (long)ED * ED, hstride, (long)ED, 1.f, 0);
    }

    // ---- scores = scale * q @ k^T  (batched over H*B = 16)
    {
        dim3 grid(SL / 256, SL / 128, NH * NB);
        gemm_tf32_kernel<true><<<grid, blk, SMEM_BYTES>>>(q, k, nullptr, sc, SL, SL, ED,
                                              (long)SL * ED, (long)SL * ED, (long)SL * SL, 0L,
                                              scale, 0);
    }

    // ---- row softmax
    softmax_kernel<<<NH * NB * SL, blk>>>(sc);

    // ---- heads = attn @ v
    {
        dim3 grid(ED / 256, SL / 128, NH * NB);
        gemm_tf32_kernel<false><<<grid, blk, SMEM_BYTES>>>(sc, v, nullptr, hd, SL, ED, SL,
                                               (long)SL * SL, (long)SL * ED, (long)SL * ED, 0L,
                                               1.f, 0);
    }

    // ---- proj = concat(heads) @ W1 + b1 == sum_h heads[h] @ W1[h*D:(h+1)*D,:]
    for (int h = 0; h < NH; h++) {
        dim3 grid(ED / 256, MT / 128, 1);
        gemm_tf32_kernel<false><<<grid, blk, SMEM_BYTES>>>(hd + (long)h * hstride,
                                               W1 + (long)h * ED * ED,
                                               (h == 0) ? b1 : nullptr, proj,
                                               MT, ED, ED, 0L, 0L, 0L, 0L,
                                               1.f, (h > 0) ? 1 : 0);
    }

    // ---- y = LN(x + proj)
    add_ln_kernel<<<MT, blk>>>(x, proj, g1, be1, y);

    // ---- t = y @ W2 + b2
    {
        dim3 grid(ED / 256, MT / 128, 1);
        gemm_tf32_kernel<false><<<grid, blk, SMEM_BYTES>>>(y, W2, b2, tp, MT, ED, ED,
                                               0L, 0L, 0L, 0L, 1.f, 0);
    }

    // ---- out = LN(y + t)
    add_ln_kernel<<<MT, blk>>>(y, tp, g2, be2, out);
}

// round 7
// speedup vs baseline: 3.1265x; 1.1813x over previous
#include <cuda_runtime.h>
#include <cstdint>

// Problem dimensions (fixed per reference)
#define ED 1024           // embedding dim D
#define NH 4              // heads
#define NB 4              // batch
#define SL 2048           // sequence length
#define MT (NB*SL)        // total tokens = 8192

// ---------------- scratch (static device globals; no allocation) -------------
__device__ float g_q[(size_t)NH*NB*SL*ED];
__device__ float g_k[(size_t)NH*NB*SL*ED];
__device__ float g_v[(size_t)NH*NB*SL*ED];
__device__ float g_scores[(size_t)NH*NB*SL*SL];
__device__ float g_heads[(size_t)NH*NB*SL*ED];
__device__ float g_proj[(size_t)MT*ED];
__device__ float g_y[(size_t)MT*ED];
__device__ float g_t[(size_t)MT*ED];

// ---------------------------------------------------------------------------
__device__ __forceinline__ void mma_tf32(float* acc, const uint32_t* a, const uint32_t* b)
{
    asm volatile(
        "mma.sync.aligned.m16n8k8.row.col.f32.tf32.tf32.f32 "
        "{%0,%1,%2,%3}, {%4,%5,%6,%7}, {%8,%9}, {%0,%1,%2,%3};"
        : "+f"(acc[0]), "+f"(acc[1]), "+f"(acc[2]), "+f"(acc[3])
        : "r"(a[0]), "r"(a[1]), "r"(a[2]), "r"(a[3]), "r"(b[0]), "r"(b[1]));
}

__device__ __forceinline__ void cp_async16(uint32_t dst, const void* src)
{
    asm volatile("cp.async.cg.shared.global [%0], [%1], 16;" :: "r"(dst), "l"(src));
}

// smem geometry (uint32 words per stage)
#define A_STRIDE 20                    // 16 k-words + pad 4  (g*20+t banks distinct)
#define BN_STRIDE 264                  // 256 + 8 (8t+g banks distinct)
#define A_WORDS   (128 * A_STRIDE)     // 2560
#define B_WORDS   (256 * A_STRIDE)     // 5120 (>= 16*264=4224, covers both layouts)
#define STAGE_WORDS (A_WORDS + B_WORDS)     // 7680
#define STAGE_BYTES (STAGE_WORDS * 4)       // 30720
#define SMEM_BYTES  (2 * STAGE_BYTES)       // 61440

// ---------------------------------------------------------------------------
// TF32 tensor-core GEMM, cp.async double-buffered.
// Block tile 128(M) x 256(N), BK=16, 512 threads = 16 warps, warp tile 32x64
// (4 M-warps x 4 N-warps), each warp = 2x8 grid of m16n8k8 mma tiles.
// Smem layouts (gmem-native, no transpose, no conversion):
//   A  : [128 rows][20]  row-major m x k        (pad 4 words)
//   B^T: [256 rows][20]  row-major n x k        (TRANSB)
//   B  : [16 rows][264]  row-major k x n        (NN)
// fp32 bits fed directly to tf32 MMA (HW truncation).
// Optional bias[N] (offset z*sBiasz), optional accumulate. Batched over z.
// Requires M % 128 == 0, N % 256 == 0, K % 16 == 0.
// ---------------------------------------------------------------------------
template <bool TRANSB>
__global__ __launch_bounds__(512) void gemm_tf32_kernel(
    const float* __restrict__ A, const float* __restrict__ Bm,
    const float* __restrict__ bias, float* __restrict__ C,
    int M, int N, int K,
    long sAz, long sBz, long sCz, long sBiasz,
    float alpha, int accumulate)
{
    extern __shared__ uint32_t smem[];

    A  += (long)blockIdx.z * sAz;
    Bm += (long)blockIdx.z * sBz;
    C  += (long)blockIdx.z * sCz;
    if (bias) bias += (long)blockIdx.z * sBiasz;

    const int tid  = threadIdx.x;
    const int lane = tid & 31;
    const int warp = tid >> 5;
    const int g    = lane >> 2;   // 0..7
    const int t    = lane & 3;    // 0..3

    const int m0 = blockIdx.y * 128;
    const int n0 = blockIdx.x * 256;
    const int wm = (warp & 3) * 32;    // M offset (0,32,64,96)
    const int wn = (warp >> 2) * 64;   // N offset (0,64,128,192)

    const uint32_t smem_u32 = (uint32_t)__cvta_generic_to_shared(smem);

    // copy-thread assignments
    const int a_row = tid >> 2, a_ch = tid & 3;          // A / B^T: row, 16B chunk

    float acc[2][8][4];
    #pragma unroll
    for (int mi = 0; mi < 2; mi++)
        #pragma unroll
        for (int ni = 0; ni < 8; ni++)
            #pragma unroll
            for (int r = 0; r < 4; r++) acc[mi][ni][r] = 0.f;

    const int KT = K >> 4;

    // ---- issue async copies for tile kt into stage
    auto issue = [&](int kt, int stage) {
        const int k0 = kt << 4;
        const uint32_t Sa = smem_u32 + stage * STAGE_BYTES;
        const uint32_t Sb = Sa + A_WORDS * 4;
        cp_async16(Sa + (a_row * A_STRIDE + a_ch * 4) * 4,
                   A + (long)(m0 + a_row) * K + k0 + a_ch * 4);
        if (TRANSB) {
            #pragma unroll
            for (int p = 0; p < 2; p++) {
                const int c = tid + p * 512, row = c >> 2, ch = c & 3;
                cp_async16(Sb + (row * A_STRIDE + ch * 4) * 4,
                           Bm + (long)(n0 + row) * K + k0 + ch * 4);
            }
        } else {
            #pragma unroll
            for (int p = 0; p < 2; p++) {
                const int c = tid + p * 512, kr = c >> 6, ch = c & 63;
                cp_async16(Sb + (kr * BN_STRIDE + ch * 4) * 4,
                           Bm + (long)(k0 + kr) * N + n0 + ch * 4);
            }
        }
        asm volatile("cp.async.commit_group;");
    };

    issue(0, 0);

    for (int kt = 0; kt < KT; kt++) {
        if (kt + 1 < KT) {
            issue(kt + 1, (kt + 1) & 1);
            asm volatile("cp.async.wait_group 1;");
        } else {
            asm volatile("cp.async.wait_group 0;");
        }
        __syncthreads();

        const uint32_t* Sa = smem + (kt & 1) * STAGE_WORDS;
        const uint32_t* Sb = Sa + A_WORDS;

        #pragma unroll
        for (int kk = 0; kk < 16; kk += 8) {
            uint32_t af[2][4], bf[8][2];
            #pragma unroll
            for (int mi = 0; mi < 2; mi++) {
                const int rb = (wm + mi * 16 + g) * A_STRIDE + kk + t;
                af[mi][0] = Sa[rb];
                af[mi][1] = Sa[rb + 8 * A_STRIDE];
                af[mi][2] = Sa[rb + 4];
                af[mi][3] = Sa[rb + 8 * A_STRIDE + 4];
            }
            if (TRANSB) {
                #pragma unroll
                for (int ni = 0; ni < 8; ni++) {
                    const int rb = (wn + ni * 8 + g) * A_STRIDE + kk + t;
                    bf[ni][0] = Sb[rb];
                    bf[ni][1] = Sb[rb + 4];
                }
            } else {
                #pragma unroll
                for (int ni = 0; ni < 8; ni++) {
                    const int nc = wn + ni * 8 + g;
                    bf[ni][0] = Sb[(kk + t) * BN_STRIDE + nc];
                    bf[ni][1] = Sb[(kk + t + 4) * BN_STRIDE + nc];
                }
            }
            #pragma unroll
            for (int mi = 0; mi < 2; mi++)
                #pragma unroll
                for (int ni = 0; ni < 8; ni++)
                    mma_tf32(acc[mi][ni], af[mi], bf[ni]);
        }
        __syncthreads();
    }

    // ---- epilogue (c0/c1 -> row g, c2/c3 -> row g+8; cols 2t, 2t+1)
    #pragma unroll
    for (int mi = 0; mi < 2; mi++) {
        #pragma unroll
        for (int ni = 0; ni < 8; ni++) {
            const int col = n0 + wn + ni * 8 + 2 * t;
            #pragma unroll
            for (int h = 0; h < 2; h++) {
                const int row = m0 + wm + mi * 16 + g + h * 8;
                float2 r;
                r.x = acc[mi][ni][h * 2 + 0] * alpha;
                r.y = acc[mi][ni][h * 2 + 1] * alpha;
                if (bias) {
                    r.x += bias[col];
                    r.y += bias[col + 1];
                }
                float* cp = C + (long)row * N + col;
                if (accumulate) {
                    float2 o = *(const float2*)cp;
                    r.x += o.x; r.y += o.y;
                }
                *(float2*)cp = r;
            }
        }
    }
}

// ---------------------------------------------------------------------------
// Single-pass row softmax over SL=2048, in place. 256 threads, 8 vals/thread.
// ---------------------------------------------------------------------------
__global__ __launch_bounds__(256) void softmax_kernel(float* __restrict__ sc)
{
    float4* p4 = (float4*)(sc + (long)blockIdx.x * SL);
    const int tid = threadIdx.x;
    const int lane = tid & 31;
    const int warp = tid >> 5;
    __shared__ float red[8];

    float4 v0 = p4[tid];
    float4 v1 = p4[tid + 256];

    float m = fmaxf(fmaxf(fmaxf(v0.x, v0.y), fmaxf(v0.z, v0.w)),
                    fmaxf(fmaxf(v1.x, v1.y), fmaxf(v1.z, v1.w)));
    #pragma unroll
    for (int s = 16; s > 0; s >>= 1) m = fmaxf(m, __shfl_xor_sync(0xffffffffu, m, s));
    if (lane == 0) red[warp] = m;
    __syncthreads();
    if (warp == 0) {
        float mm = red[lane & 7];
        #pragma unroll
        for (int s = 4; s > 0; s >>= 1) mm = fmaxf(mm, __shfl_xor_sync(0xffffffffu, mm, s));
        if (lane == 0) red[0] = mm;
    }
    __syncthreads();
    const float mv = red[0];
    __syncthreads();

    v0.x = __expf(v0.x - mv); v0.y = __expf(v0.y - mv);
    v0.z = __expf(v0.z - mv); v0.w = __expf(v0.w - mv);
    v1.x = __expf(v1.x - mv); v1.y = __expf(v1.y - mv);
    v1.z = __expf(v1.z - mv); v1.w = __expf(v1.w - mv);
    float s = v0.x + v0.y + v0.z + v0.w + v1.x + v1.y + v1.z + v1.w;
    #pragma unroll
    for (int st = 16; st > 0; st >>= 1) s += __shfl_xor_sync(0xffffffffu, s, st);
    if (lane == 0) red[warp] = s;
    __syncthreads();
    if (warp == 0) {
        float ss = red[lane & 7];
        #pragma unroll
        for (int st = 4; st > 0; st >>= 1) ss += __shfl_xor_sync(0xffffffffu, ss, st);
        if (lane == 0) red[0] = ss;
    }
    __syncthreads();
    const float inv = 1.f / red[0];

    v0.x *= inv; v0.y *= inv; v0.z *= inv; v0.w *= inv;
    v1.x *= inv; v1.y *= inv; v1.z *= inv; v1.w *= inv;
    p4[tid] = v0;
    p4[tid + 256] = v1;
}

// ---------------------------------------------------------------------------
// out = LayerNorm(X + R) * g + b, row length ED, one block per row.
// ---------------------------------------------------------------------------
__global__ __launch_bounds__(256) void add_ln_kernel(
    const float* __restrict__ X, const float* __restrict__ R,
    const float* __restrict__ g, const float* __restrict__ b,
    float* __restrict__ out)
{
    const long row = blockIdx.x;
    const float* x = X + row * ED;
    const float* r = R + row * ED;
    float* o = out + row * ED;
    const int t = threadIdx.x;

    float v[4];
    float s = 0.f, s2 = 0.f;
    #pragma unroll
    for (int i = 0; i < 4; i++) {
        float h = x[t + i * 256] + r[t + i * 256];
        v[i] = h;
        s += h;
        s2 += h * h;
    }
    __shared__ float rs[256], rq[256];
    rs[t] = s; rq[t] = s2; __syncthreads();
    for (int st = 128; st > 0; st >>= 1) {
        if (t < st) { rs[t] += rs[t + st]; rq[t] += rq[t + st]; }
        __syncthreads();
    }
    const float mean = rs[0] * (1.f / ED);
    const float var  = rq[0] * (1.f / ED) - mean * mean;
    const float inv  = rsqrtf(var + 1e-5f);
    #pragma unroll
    for (int i = 0; i < 4; i++) {
        int c = t + i * 256;
        o[c] = (v[i] - mean) * inv * g[c] + b[c];
    }
}

// ---------------------------------------------------------------------------
extern "C" void kernel_launch(void* const* d_in, const int* in_sizes, int n_in,
                              void* d_out, int out_size)
{
    const float* x   = (const float*)d_in[0];
    const float* Wq  = (const float*)d_in[1];
    const float* bq  = (const float*)d_in[2];
    const float* Wk  = (const float*)d_in[3];
    const float* bk  = (const float*)d_in[4];
    const float* Wv  = (const float*)d_in[5];
    const float* bv  = (const float*)d_in[6];
    const float* W1  = (const float*)d_in[7];
    const float* b1  = (const float*)d_in[8];
    const float* g1  = (const float*)d_in[9];
    const float* be1 = (const float*)d_in[10];
    const float* W2  = (const float*)d_in[11];
    const float* b2  = (const float*)d_in[12];
    const float* g2  = (const float*)d_in[13];
    const float* be2 = (const float*)d_in[14];
    float* out = (float*)d_out;

    float *q, *k, *v, *sc, *hd, *proj, *y, *tp;
    cudaGetSymbolAddress((void**)&q,    g_q);
    cudaGetSymbolAddress((void**)&k,    g_k);
    cudaGetSymbolAddress((void**)&v,    g_v);
    cudaGetSymbolAddress((void**)&sc,   g_scores);
    cudaGetSymbolAddress((void**)&hd,   g_heads);
    cudaGetSymbolAddress((void**)&proj, g_proj);
    cudaGetSymbolAddress((void**)&y,    g_y);
    cudaGetSymbolAddress((void**)&tp,   g_t);

    cudaFuncSetAttribute(gemm_tf32_kernel<false>,
                         cudaFuncAttributeMaxDynamicSharedMemorySize, SMEM_BYTES);
    cudaFuncSetAttribute(gemm_tf32_kernel<true>,
                         cudaFuncAttributeMaxDynamicSharedMemorySize, SMEM_BYTES);

    const float scale = 1.0f / 32.0f;   // 1/sqrt(1024)
    const long  hstride = (long)NB * SL * ED;
    dim3 blk(512);

    // ---- per-head Q/K/V projections (batched over H); bias offset h*ED
    {
        dim3 grid(ED / 256, MT / 128, NH);
        gemm_tf32_kernel<false><<<grid, blk, SMEM_BYTES>>>(x, Wq, bq, q, MT, ED, ED,
                                               0L, (long)ED * ED, hstride, (long)ED, 1.f, 0);
        gemm_tf32_kernel<false><<<grid, blk, SMEM_BYTES>>>(x, Wk, bk, k, MT, ED, ED,
                                               0L, (long)ED * ED, hstride, (long)ED, 1.f, 0);
        gemm_tf32_kernel<false><<<grid, blk, SMEM_BYTES>>>(x, Wv, bv, v, MT, ED, ED,
                                               0L, (long)ED * ED, hstride, (long)ED, 1.f, 0);
    }

    // ---- scores = scale * q @ k^T  (batched over H*B = 16)
    {
        dim3 grid(SL / 256, SL / 128, NH * NB);
        gemm_tf32_kernel<true><<<grid, blk, SMEM_BYTES>>>(q, k, nullptr, sc, SL, SL, ED,
                                              (long)SL * ED, (long)SL * ED, (long)SL * SL, 0L,
                                              scale, 0);
    }

    // ---- row softmax
    softmax_kernel<<<NH * NB * SL, 256>>>(sc);

    // ---- heads = attn @ v
    {
        dim3 grid(ED / 256, SL / 128, NH * NB);
        gemm_tf32_kernel<false><<<grid, blk, SMEM_BYTES>>>(sc, v, nullptr, hd, SL, ED, SL,
                                               (long)SL * SL, (long)SL * ED, (long)SL * ED, 0L,
                                               1.f, 0);
    }

    // ---- proj = concat(heads) @ W1 + b1 == sum_h heads[h] @ W1[h*D:(h+1)*D,:]
    for (int h = 0; h < NH; h++) {
        dim3 grid(ED / 256, MT / 128, 1);
        gemm_tf32_kernel<false><<<grid, blk, SMEM_BYTES>>>(hd + (long)h * hstride,
                                               W1 + (long)h * ED * ED,
                                               (h == 0) ? b1 : nullptr, proj,
                                               MT, ED, ED, 0L, 0L, 0L, 0L,
                                               1.f, (h > 0) ? 1 : 0);
    }

    // ---- y = LN(x + proj)
    add_ln_kernel<<<MT, 256>>>(x, proj, g1, be1, y);

    // ---- t = y @ W2 + b2
    {
        dim3 grid(ED / 256, MT / 128, 1);
        gemm_tf32_kernel<false><<<grid, blk, SMEM_BYTES>>>(y, W2, b2, tp, MT, ED, ED,
                                               0L, 0L, 0L, 0L, 1.f, 0);
    }

    // ---- out = LN(y + t)
    add_ln_kernel<<<MT, 256>>>(y, tp, g2, be2, out);
}

// round 8
// speedup vs baseline: 3.3665x; 1.0767x over previous
#include <cuda_runtime.h>
#include <cstdint>

// Problem dimensions (fixed per reference)
#define ED 1024           // embedding dim D
#define NH 4              // heads
#define NB 4              // batch
#define SL 2048           // sequence length
#define MT (NB*SL)        // total tokens = 8192

// ---------------- scratch (static device globals; no allocation) -------------
__device__ float g_q[(size_t)NH*NB*SL*ED];
__device__ float g_k[(size_t)NH*NB*SL*ED];
__device__ float g_v[(size_t)NH*NB*SL*ED];
__device__ float g_scores[(size_t)NH*NB*SL*SL];
__device__ float g_heads[(size_t)NH*NB*SL*ED];
__device__ float g_proj[(size_t)MT*ED];
__device__ float g_y[(size_t)MT*ED];
__device__ float g_t[(size_t)MT*ED];

// ---------------------------------------------------------------------------
__device__ __forceinline__ void mma_tf32(float* acc, const uint32_t* a, const uint32_t* b)
{
    asm volatile(
        "mma.sync.aligned.m16n8k8.row.col.f32.tf32.tf32.f32 "
        "{%0,%1,%2,%3}, {%4,%5,%6,%7}, {%8,%9}, {%0,%1,%2,%3};"
        : "+f"(acc[0]), "+f"(acc[1]), "+f"(acc[2]), "+f"(acc[3])
        : "r"(a[0]), "r"(a[1]), "r"(a[2]), "r"(a[3]), "r"(b[0]), "r"(b[1]));
}

__device__ __forceinline__ void cp_async16(uint32_t dst, const void* src)
{
    asm volatile("cp.async.cg.shared.global [%0], [%1], 16;" :: "r"(dst), "l"(src));
}

// smem geometry (uint32 words per stage)
#define A_STRIDE 20                    // 16 k-words + pad 4  (conflict-free)
#define BN_STRIDE 264                  // 256 + 8
#define A_WORDS   (128 * A_STRIDE)     // 2560
#define B_WORDS   (256 * A_STRIDE)     // 5120 (>= 16*264=4224, covers both layouts)
#define STAGE_WORDS (A_WORDS + B_WORDS)     // 7680
#define STAGE_BYTES (STAGE_WORDS * 4)       // 30720
#define NSTAGE 4
#define SMEM_BYTES  (NSTAGE * STAGE_BYTES)  // 122880

// ---------------------------------------------------------------------------
// TF32 tensor-core GEMM, 4-stage cp.async pipeline, one barrier per k-iter.
// Block tile 128(M) x 256(N), BK=16, 512 threads = 16 warps, warp tile 32x64
// (4 M-warps x 4 N-warps), each warp = 2x8 grid of m16n8k8 mma tiles.
// Smem layouts (gmem-native, no transpose, no conversion):
//   A  : [128 rows][20]  row-major m x k
//   B^T: [256 rows][20]  row-major n x k        (TRANSB)
//   B  : [16 rows][264]  row-major k x n        (NN)
// fp32 bits fed directly to tf32 MMA (HW truncation).
// Optional bias[N] (offset z*sBiasz), optional accumulate. Batched over z.
// Requires M % 128 == 0, N % 256 == 0, K % 16 == 0.
// ---------------------------------------------------------------------------
template <bool TRANSB>
__global__ __launch_bounds__(512) void gemm_tf32_kernel(
    const float* __restrict__ A, const float* __restrict__ Bm,
    const float* __restrict__ bias, float* __restrict__ C,
    int M, int N, int K,
    long sAz, long sBz, long sCz, long sBiasz,
    float alpha, int accumulate)
{
    extern __shared__ uint32_t smem[];

    A  += (long)blockIdx.z * sAz;
    Bm += (long)blockIdx.z * sBz;
    C  += (long)blockIdx.z * sCz;
    if (bias) bias += (long)blockIdx.z * sBiasz;

    const int tid  = threadIdx.x;
    const int lane = tid & 31;
    const int warp = tid >> 5;
    const int g    = lane >> 2;   // 0..7
    const int t    = lane & 3;    // 0..3

    const int m0 = blockIdx.y * 128;
    const int n0 = blockIdx.x * 256;
    const int wm = (warp & 3) * 32;    // M offset (0,32,64,96)
    const int wn = (warp >> 2) * 64;   // N offset (0,64,128,192)

    const uint32_t smem_u32 = (uint32_t)__cvta_generic_to_shared(smem);

    // copy-thread assignments
    const int a_row = tid >> 2, a_ch = tid & 3;          // A / B^T: row, 16B chunk

    float acc[2][8][4];
    #pragma unroll
    for (int mi = 0; mi < 2; mi++)
        #pragma unroll
        for (int ni = 0; ni < 8; ni++)
            #pragma unroll
            for (int r = 0; r < 4; r++) acc[mi][ni][r] = 0.f;

    const int KT = K >> 4;

    // ---- issue async copies for tile kt (guarded); ALWAYS commits a group
    auto issue = [&](int kt) {
        if (kt < KT) {
            const int k0 = kt << 4;
            const int stage = kt & (NSTAGE - 1);
            const uint32_t Sa = smem_u32 + stage * STAGE_BYTES;
            const uint32_t Sb = Sa + A_WORDS * 4;
            cp_async16(Sa + (a_row * A_STRIDE + a_ch * 4) * 4,
                       A + (long)(m0 + a_row) * K + k0 + a_ch * 4);
            if (TRANSB) {
                #pragma unroll
                for (int p = 0; p < 2; p++) {
                    const int c = tid + p * 512, row = c >> 2, ch = c & 3;
                    cp_async16(Sb + (row * A_STRIDE + ch * 4) * 4,
                               Bm + (long)(n0 + row) * K + k0 + ch * 4);
                }
            } else {
                #pragma unroll
                for (int p = 0; p < 2; p++) {
                    const int c = tid + p * 512, kr = c >> 6, ch = c & 63;
                    cp_async16(Sb + (kr * BN_STRIDE + ch * 4) * 4,
                               Bm + (long)(k0 + kr) * N + n0 + ch * 4);
                }
            }
        }
        asm volatile("cp.async.commit_group;");
    };

    // prologue: 3 tiles in flight
    issue(0); issue(1); issue(2);

    for (int kt = 0; kt < KT; kt++) {
        // retire until stage kt is resident (<=2 groups pending)
        asm volatile("cp.async.wait_group 2;");
        __syncthreads();      // also protects stage (kt+3)&3 from WAR below

        issue(kt + 3);

        const uint32_t* Sa = smem + (kt & (NSTAGE - 1)) * STAGE_WORDS;
        const uint32_t* Sb = Sa + A_WORDS;

        #pragma unroll
        for (int kk = 0; kk < 16; kk += 8) {
            uint32_t af[2][4], bf[8][2];
            #pragma unroll
            for (int mi = 0; mi < 2; mi++) {
                const int rb = (wm + mi * 16 + g) * A_STRIDE + kk + t;
                af[mi][0] = Sa[rb];
                af[mi][1] = Sa[rb + 8 * A_STRIDE];
                af[mi][2] = Sa[rb + 4];
                af[mi][3] = Sa[rb + 8 * A_STRIDE + 4];
            }
            if (TRANSB) {
                #pragma unroll
                for (int ni = 0; ni < 8; ni++) {
                    const int rb = (wn + ni * 8 + g) * A_STRIDE + kk + t;
                    bf[ni][0] = Sb[rb];
                    bf[ni][1] = Sb[rb + 4];
                }
            } else {
                #pragma unroll
                for (int ni = 0; ni < 8; ni++) {
                    const int nc = wn + ni * 8 + g;
                    bf[ni][0] = Sb[(kk + t) * BN_STRIDE + nc];
                    bf[ni][1] = Sb[(kk + t + 4) * BN_STRIDE + nc];
                }
            }
            #pragma unroll
            for (int mi = 0; mi < 2; mi++)
                #pragma unroll
                for (int ni = 0; ni < 8; ni++)
                    mma_tf32(acc[mi][ni], af[mi], bf[ni]);
        }
    }

    // ---- epilogue (c0/c1 -> row g, c2/c3 -> row g+8; cols 2t, 2t+1)
    #pragma unroll
    for (int mi = 0; mi < 2; mi++) {
        #pragma unroll
        for (int ni = 0; ni < 8; ni++) {
            const int col = n0 + wn + ni * 8 + 2 * t;
            #pragma unroll
            for (int h = 0; h < 2; h++) {
                const int row = m0 + wm + mi * 16 + g + h * 8;
                float2 r;
                r.x = acc[mi][ni][h * 2 + 0] * alpha;
                r.y = acc[mi][ni][h * 2 + 1] * alpha;
                if (bias) {
                    r.x += bias[col];
                    r.y += bias[col + 1];
                }
                float* cp = C + (long)row * N + col;
                if (accumulate) {
                    float2 o = *(const float2*)cp;
                    r.x += o.x; r.y += o.y;
                }
                *(float2*)cp = r;
            }
        }
    }
}

// ---------------------------------------------------------------------------
// Single-pass row softmax over SL=2048, in place. 256 threads, 8 vals/thread.
// ---------------------------------------------------------------------------
__global__ __launch_bounds__(256) void softmax_kernel(float* __restrict__ sc)
{
    float4* p4 = (float4*)(sc + (long)blockIdx.x * SL);
    const int tid = threadIdx.x;
    const int lane = tid & 31;
    const int warp = tid >> 5;
    __shared__ float red[8];

    float4 v0 = p4[tid];
    float4 v1 = p4[tid + 256];

    float m = fmaxf(fmaxf(fmaxf(v0.x, v0.y), fmaxf(v0.z, v0.w)),
                    fmaxf(fmaxf(v1.x, v1.y), fmaxf(v1.z, v1.w)));
    #pragma unroll
    for (int s = 16; s > 0; s >>= 1) m = fmaxf(m, __shfl_xor_sync(0xffffffffu, m, s));
    if (lane == 0) red[warp] = m;
    __syncthreads();
    if (warp == 0) {
        float mm = red[lane & 7];
        #pragma unroll
        for (int s = 4; s > 0; s >>= 1) mm = fmaxf(mm, __shfl_xor_sync(0xffffffffu, mm, s));
        if (lane == 0) red[0] = mm;
    }
    __syncthreads();
    const float mv = red[0];
    __syncthreads();

    v0.x = __expf(v0.x - mv); v0.y = __expf(v0.y - mv);
    v0.z = __expf(v0.z - mv); v0.w = __expf(v0.w - mv);
    v1.x = __expf(v1.x - mv); v1.y = __expf(v1.y - mv);
    v1.z = __expf(v1.z - mv); v1.w = __expf(v1.w - mv);
    float s = v0.x + v0.y + v0.z + v0.w + v1.x + v1.y + v1.z + v1.w;
    #pragma unroll
    for (int st = 16; st > 0; st >>= 1) s += __shfl_xor_sync(0xffffffffu, s, st);
    if (lane == 0) red[warp] = s;
    __syncthreads();
    if (warp == 0) {
        float ss = red[lane & 7];
        #pragma unroll
        for (int st = 4; st > 0; st >>= 1) ss += __shfl_xor_sync(0xffffffffu, ss, st);
        if (lane == 0) red[0] = ss;
    }
    __syncthreads();
    const float inv = 1.f / red[0];

    v0.x *= inv; v0.y *= inv; v0.z *= inv; v0.w *= inv;
    v1.x *= inv; v1.y *= inv; v1.z *= inv; v1.w *= inv;
    p4[tid] = v0;
    p4[tid + 256] = v1;
}

// ---------------------------------------------------------------------------
// out = LayerNorm(X + R) * g + b, row length ED, one block per row.
// ---------------------------------------------------------------------------
__global__ __launch_bounds__(256) void add_ln_kernel(
    const float* __restrict__ X, const float* __restrict__ R,
    const float* __restrict__ g, const float* __restrict__ b,
    float* __restrict__ out)
{
    const long row = blockIdx.x;
    const float* x = X + row * ED;
    const float* r = R + row * ED;
    float* o = out + row * ED;
    const int t = threadIdx.x;

    float v[4];
    float s = 0.f, s2 = 0.f;
    #pragma unroll
    for (int i = 0; i < 4; i++) {
        float h = x[t + i * 256] + r[t + i * 256];
        v[i] = h;
        s += h;
        s2 += h * h;
    }
    __shared__ float rs[256], rq[256];
    rs[t] = s; rq[t] = s2; __syncthreads();
    for (int st = 128; st > 0; st >>= 1) {
        if (t < st) { rs[t] += rs[t + st]; rq[t] += rq[t + st]; }
        __syncthreads();
    }
    const float mean = rs[0] * (1.f / ED);
    const float var  = rq[0] * (1.f / ED) - mean * mean;
    const float inv  = rsqrtf(var + 1e-5f);
    #pragma unroll
    for (int i = 0; i < 4; i++) {
        int c = t + i * 256;
        o[c] = (v[i] - mean) * inv * g[c] + b[c];
    }
}

// ---------------------------------------------------------------------------
extern "C" void kernel_launch(void* const* d_in, const int* in_sizes, int n_in,
                              void* d_out, int out_size)
{
    const float* x   = (const float*)d_in[0];
    const float* Wq  = (const float*)d_in[1];
    const float* bq  = (const float*)d_in[2];
    const float* Wk  = (const float*)d_in[3];
    const float* bk  = (const float*)d_in[4];
    const float* Wv  = (const float*)d_in[5];
    const float* bv  = (const float*)d_in[6];
    const float* W1  = (const float*)d_in[7];
    const float* b1  = (const float*)d_in[8];
    const float* g1  = (const float*)d_in[9];
    const float* be1 = (const float*)d_in[10];
    const float* W2  = (const float*)d_in[11];
    const float* b2  = (const float*)d_in[12];
    const float* g2  = (const float*)d_in[13];
    const float* be2 = (const float*)d_in[14];
    float* out = (float*)d_out;

    float *q, *k, *v, *sc, *hd, *proj, *y, *tp;
    cudaGetSymbolAddress((void**)&q,    g_q);
    cudaGetSymbolAddress((void**)&k,    g_k);
    cudaGetSymbolAddress((void**)&v,    g_v);
    cudaGetSymbolAddress((void**)&sc,   g_scores);
    cudaGetSymbolAddress((void**)&hd,   g_heads);
    cudaGetSymbolAddress((void**)&proj, g_proj);
    cudaGetSymbolAddress((void**)&y,    g_y);
    cudaGetSymbolAddress((void**)&tp,   g_t);

    cudaFuncSetAttribute(gemm_tf32_kernel<false>,
                         cudaFuncAttributeMaxDynamicSharedMemorySize, SMEM_BYTES);
    cudaFuncSetAttribute(gemm_tf32_kernel<true>,
                         cudaFuncAttributeMaxDynamicSharedMemorySize, SMEM_BYTES);

    const float scale = 1.0f / 32.0f;   // 1/sqrt(1024)
    const long  hstride = (long)NB * SL * ED;
    dim3 blk(512);

    // ---- per-head Q/K/V projections (batched over H); bias offset h*ED
    {
        dim3 grid(ED / 256, MT / 128, NH);
        gemm_tf32_kernel<false><<<grid, blk, SMEM_BYTES>>>(x, Wq, bq, q, MT, ED, ED,
                                               0L, (long)ED * ED, hstride, (long)ED, 1.f, 0);
        gemm_tf32_kernel<false><<<grid, blk, SMEM_BYTES>>>(x, Wk, bk, k, MT, ED, ED,
                                               0L, (long)ED * ED, hstride, (long)ED, 1.f, 0);
        gemm_tf32_kernel<false><<<grid, blk, SMEM_BYTES>>>(x, Wv, bv, v, MT, ED, ED,
                                               0L, (long)ED * ED, hstride, (long)ED, 1.f, 0);
    }

    // ---- scores = scale * q @ k^T  (batched over H*B = 16)
    {
        dim3 grid(SL / 256, SL / 128, NH * NB);
        gemm_tf32_kernel<true><<<grid, blk, SMEM_BYTES>>>(q, k, nullptr, sc, SL, SL, ED,
                                              (long)SL * ED, (long)SL * ED, (long)SL * SL, 0L,
                                              scale, 0);
    }

    // ---- row softmax
    softmax_kernel<<<NH * NB * SL, 256>>>(sc);

    // ---- heads = attn @ v
    {
        dim3 grid(ED / 256, SL / 128, NH * NB);
        gemm_tf32_kernel<false><<<grid, blk, SMEM_BYTES>>>(sc, v, nullptr, hd, SL, ED, SL,
                                               (long)SL * SL, (long)SL * ED, (long)SL * ED, 0L,
                                               1.f, 0);
    }

    // ---- proj = concat(heads) @ W1 + b1 == sum_h heads[h] @ W1[h*D:(h+1)*D,:]
    for (int h = 0; h < NH; h++) {
        dim3 grid(ED / 256, MT / 128, 1);
        gemm_tf32_kernel<false><<<grid, blk, SMEM_BYTES>>>(hd + (long)h * hstride,
                                               W1 + (long)h * ED * ED,
                                               (h == 0) ? b1 : nullptr, proj,
                                               MT, ED, ED, 0L, 0L, 0L, 0L,
                                               1.f, (h > 0) ? 1 : 0);
    }

    // ---- y = LN(x + proj)
    add_ln_kernel<<<MT, 256>>>(x, proj, g1, be1, y);

    // ---- t = y @ W2 + b2
    {
        dim3 grid(ED / 256, MT / 128, 1);
        gemm_tf32_kernel<false><<<grid, blk, SMEM_BYTES>>>(y, W2, b2, tp, MT, ED, ED,
                                               0L, 0L, 0L, 0L, 1.f, 0);
    }

    // ---- out = LN(y + t)
    add_ln_kernel<<<MT, 256>>>(y, tp, g2, be2, out);
}